// round 4
// baseline (speedup 1.0000x reference)
#include <cuda_runtime.h>
#include <cuda_fp16.h>
#include <cstdint>

// ============================================================================
// out_i = || P * U(params) * s_i ||^2, 131072 states of dim 256.
// params are batch-invariant -> precompute A = P*U (128x256 complex) once,
// then a real GEMM with fp16 mma.sync (tcgen05 unavailable: harness PTX
// targets compute_103 base, not sm_103a):
//   S = [sr | si]  (131072 x 512 fp32, converted to fp16 on the fly)
//   Wh[n][k] fp16 (256 x 512), n<128: [Ar | -Ai], n>=128: [Ai | Ar]
//   C[m][n] = sum_k S[m][k] Wh[n][k];  out_m = sum_n C[m][n]^2
//
// R4: occupancy fix. CTA tile 64x256 (was 128x256), warp tile 32x32,
//     launch_bounds(512,2) -> <=64 regs -> 2 CTAs/SM (occ 25%->50%).
//     build_weights rewritten warp-resident (no __syncthreads).
// ============================================================================

#define NLAYERS 3
#define NQ 8

__device__ __half Wh_global[256 * 512];

// ---------------------------------------------------------------------------
__device__ __forceinline__ uint32_t smem_u32(const void* p) {
    uint32_t a;
    asm("{ .reg .u64 t; cvta.to.shared.u64 t, %1; cvt.u32.u64 %0, t; }"
        : "=r"(a) : "l"(p));
    return a;
}

__device__ __forceinline__ void ldmatrix_x4(uint32_t r[4], uint32_t addr) {
    asm volatile("ldmatrix.sync.aligned.m8n8.x4.shared.b16 {%0,%1,%2,%3}, [%4];"
                 : "=r"(r[0]), "=r"(r[1]), "=r"(r[2]), "=r"(r[3]) : "r"(addr));
}

__device__ __forceinline__ void mma16816(float c[4], const uint32_t a[4],
                                         uint32_t b0, uint32_t b1) {
    asm volatile(
        "mma.sync.aligned.m16n8k16.row.col.f32.f16.f16.f32 "
        "{%0,%1,%2,%3}, {%4,%5,%6,%7}, {%8,%9}, {%0,%1,%2,%3};"
        : "+f"(c[0]), "+f"(c[1]), "+f"(c[2]), "+f"(c[3])
        : "r"(a[0]), "r"(a[1]), "r"(a[2]), "r"(a[3]), "r"(b0), "r"(b1));
}

__device__ __forceinline__ void cp_async16(uint32_t dst, const void* src) {
    asm volatile("cp.async.cg.shared.global [%0], [%1], 16;"
                 :: "r"(dst), "l"(src) : "memory");
}
#define CP_COMMIT() asm volatile("cp.async.commit_group;" ::: "memory")
#define CP_WAIT0()  asm volatile("cp.async.wait_group 0;" ::: "memory")

// ---------------------------------------------------------------------------
// Setup: warp-resident circuit simulation. One warp simulates one basis
// column k; the 256 complex amps live in registers (8 float2 per lane,
// amp index i = (lane<<3)|r). Butterflies across lanes via shfl.xor.
// Fully unrolled so every gate's bit position is compile-time.
// ---------------------------------------------------------------------------
__global__ void __launch_bounds__(256)
build_weights_kernel(const float* __restrict__ params) {
    const int lane = threadIdx.x & 31;
    const int wid  = threadIdx.x >> 5;
    const int k    = blockIdx.x * 8 + wid;   // column 0..255

    float2 st[8];
    #pragma unroll
    for (int r = 0; r < 8; r++) {
        int i = (lane << 3) | r;
        st[r] = make_float2(i == k ? 1.0f : 0.0f, 0.0f);
    }

    #pragma unroll
    for (int l = 0; l < NLAYERS; l++) {
        // ---- single-qubit rotations ----
        #pragma unroll
        for (int q = 0; q < NQ; q++) {
            const float* pr = params + (l * NQ + q) * 3;
            float hx = 0.5f * pr[0], hy = 0.5f * pr[1], hz = 0.5f * pr[2];
            float cx = cosf(hx), sx = sinf(hx);
            float cy = cosf(hy), sy = sinf(hy);
            float cz = cosf(hz), sz = sinf(hz);
            float m00r =  cy * cx, m00i =  sy * sx;
            float m01r = -sy * cx, m01i = -cy * sx;
            float m10r =  sy * cx, m10i = -cy * sx;
            float m11r =  cy * cx, m11i = -sy * sx;
            float u00r = cz * m00r + sz * m00i, u00i = cz * m00i - sz * m00r;
            float u01r = cz * m01r + sz * m01i, u01i = cz * m01i - sz * m01r;
            float u10r = cz * m10r - sz * m10i, u10i = cz * m10i + sz * m10r;
            float u11r = cz * m11r - sz * m11i, u11i = cz * m11i + sz * m11r;
            const int p = 7 - q;  // qubit 0 = MSB of flat index

            if (p < 3) {
                const int m = 1 << p;
                #pragma unroll
                for (int r = 0; r < 8; r++) {
                    if ((r & m) == 0) {
                        int r1 = r | m;
                        float2 a0 = st[r], a1 = st[r1];
                        float2 n0, n1;
                        n0.x = u00r*a0.x - u00i*a0.y + u01r*a1.x - u01i*a1.y;
                        n0.y = u00r*a0.y + u00i*a0.x + u01r*a1.y + u01i*a1.x;
                        n1.x = u10r*a0.x - u10i*a0.y + u11r*a1.x - u11i*a1.y;
                        n1.y = u10r*a0.y + u10i*a0.x + u11r*a1.y + u11i*a1.x;
                        st[r]  = n0;
                        st[r1] = n1;
                    }
                }
            } else {
                const int lm = 1 << (p - 3);
                const bool hi = (lane & lm) != 0;
                float car = hi ? u10r : u00r, cai = hi ? u10i : u00i;
                float cbr = hi ? u11r : u01r, cbi = hi ? u11i : u01i;
                #pragma unroll
                for (int r = 0; r < 8; r++) {
                    float ox = __shfl_xor_sync(0xFFFFFFFFu, st[r].x, lm);
                    float oy = __shfl_xor_sync(0xFFFFFFFFu, st[r].y, lm);
                    float a0x = hi ? ox : st[r].x, a0y = hi ? oy : st[r].y;
                    float a1x = hi ? st[r].x : ox, a1y = hi ? st[r].y : oy;
                    st[r].x = car*a0x - cai*a0y + cbr*a1x - cbi*a1y;
                    st[r].y = car*a0y + cai*a0x + cbr*a1y + cbi*a1x;
                }
            }
        }
        // ---- CNOT ring: ctrl q, tgt (q+1)%8 ----
        #pragma unroll
        for (int q = 0; q < NQ; q++) {
            const int pc = 7 - q;
            const int pt = 7 - ((q + 1) & 7);

            if (pt < 3) {
                const int mt = 1 << pt;
                if (pc < 3) {
                    const int mc = 1 << pc;
                    #pragma unroll
                    for (int r = 0; r < 8; r++) {
                        if ((r & mc) != 0 && (r & mt) == 0) {
                            float2 t = st[r]; st[r] = st[r | mt]; st[r | mt] = t;
                        }
                    }
                } else {
                    const int lmc = 1 << (pc - 3);
                    const bool sel = (lane & lmc) != 0;
                    #pragma unroll
                    for (int r = 0; r < 8; r++) {
                        if ((r & mt) == 0) {
                            int r1 = r | mt;
                            float2 a = st[r], b = st[r1];
                            st[r]  = sel ? b : a;
                            st[r1] = sel ? a : b;
                        }
                    }
                }
            } else {
                const int lmt = 1 << (pt - 3);
                if (pc < 3) {
                    const int mc = 1 << pc;
                    #pragma unroll
                    for (int r = 0; r < 8; r++) {
                        float ox = __shfl_xor_sync(0xFFFFFFFFu, st[r].x, lmt);
                        float oy = __shfl_xor_sync(0xFFFFFFFFu, st[r].y, lmt);
                        if ((r & mc) != 0) { st[r].x = ox; st[r].y = oy; }
                    }
                } else {
                    const int lmc = 1 << (pc - 3);
                    const bool sel = (lane & lmc) != 0;
                    #pragma unroll
                    for (int r = 0; r < 8; r++) {
                        float ox = __shfl_xor_sync(0xFFFFFFFFu, st[r].x, lmt);
                        float oy = __shfl_xor_sync(0xFFFFFFFFu, st[r].y, lmt);
                        if (sel) { st[r].x = ox; st[r].y = oy; }
                    }
                }
            }
        }
    }

    // rows i < 128  <=>  lane < 16
    if (lane < 16) {
        #pragma unroll
        for (int r = 0; r < 8; r++) {
            int i = (lane << 3) | r;
            float re = st[r].x, im = st[r].y;
            Wh_global[i * 512 + k]               = __float2half_rn(re);
            Wh_global[i * 512 + 256 + k]         = __float2half_rn(-im);
            Wh_global[(128 + i) * 512 + k]       = __float2half_rn(im);
            Wh_global[(128 + i) * 512 + 256 + k] = __float2half_rn(re);
        }
    }
}

// ---------------------------------------------------------------------------
// GEMM kernel: CTA = 64 batch rows x 256 N. 512 threads = 16 warps,
// warp grid 2(M) x 8(N), warp tile 32x32. K = 512 in 8 chunks of 64.
// SMEM per buffer: A 64x64 fp16 (8KB, 128B swizzled rows) at +0,
//                  B 256x64 fp16 (32KB) at +8KB. Two buffers (80KB).
// 2 CTAs/SM (regs capped at 64 via launch_bounds).
// ---------------------------------------------------------------------------
static constexpr uint32_t BS_OFF    = 8 * 1024;
static constexpr uint32_t BUF_BYTES = 40 * 1024;
static constexpr uint32_t RED_OFF   = 80 * 1024;
static constexpr uint32_t DYN_SMEM  = 80 * 1024 + 256 + 1024;

__global__ void __launch_bounds__(512, 2)
qmm_kernel(const float* __restrict__ sre, const float* __restrict__ sim,
           float* __restrict__ out) {
    extern __shared__ char smem_raw[];
    uint32_t base  = smem_u32(smem_raw);
    uint32_t abase = (base + 1023u) & ~1023u;
    char* a = smem_raw + (abase - base);
    float* red = (float*)(a + RED_OFF);

    const int tid  = threadIdx.x;
    const int wid  = tid >> 5;
    const int lane = tid & 31;
    const int wm   = wid & 1;   // m-half: rows wm*32..+31
    const int wn   = wid >> 1;  // n-slice: cols wn*32..+31

    // ldmatrix per-lane geometry
    const int r  = lane & 7;
    const int q  = lane >> 3;
    const uint32_t xorv = (uint32_t)r << 4;
    const uint32_t ch16 = (uint32_t)(q >> 1) << 4;
    const int rl = ((q & 1) << 3) + r;  // row within 16-row fragment

    uint32_t aRow[2], bRow[2];
    #pragma unroll
    for (int mf = 0; mf < 2; mf++)
        aRow[mf] = abase + (uint32_t)(wm * 32 + mf * 16 + rl) * 128;
    #pragma unroll
    for (int nb = 0; nb < 2; nb++)
        bRow[nb] = abase + BS_OFF + (uint32_t)(wn * 32 + nb * 16 + rl) * 128;

    const long tileBase = (long)blockIdx.x * 64;

    float acc[2][4][4];
    #pragma unroll
    for (int mf = 0; mf < 2; mf++)
        #pragma unroll
        for (int nf = 0; nf < 4; nf++)
            #pragma unroll
            for (int i = 0; i < 4; i++) acc[mf][nf][i] = 0.0f;

    // A global-load prefetch registers: 64 rows x 16 float4 = 1024 float4,
    // 512 threads -> 2 per thread. i = tid + it*512 -> row = i>>4, f4 = i&15.
    float4 av[2];

    // ---- prologue: chunk 0 ----
    {
        #pragma unroll
        for (int it = 0; it < 2; it++) {
            int i = tid + it * 512;
            int row = i >> 4, f4 = i & 15;
            av[it] = *(const float4*)(sre + (tileBase + row) * 256 + f4 * 4);
        }
        // B: 256 rows x 8 segs of 16B = 2048, 512 threads -> 4 per thread
        #pragma unroll
        for (int it = 0; it < 4; it++) {
            int i = tid + it * 512;
            int n = i >> 3, seg = i & 7;
            uint32_t dst = abase + BS_OFF +
                           (uint32_t)n * 128 +
                           (((uint32_t)seg * 16) ^ (((uint32_t)n & 7) << 4));
            cp_async16(dst, Wh_global + n * 512 + seg * 8);
        }
        CP_COMMIT();
    }

    for (int c = 0; c < 8; c++) {
        const int b = c & 1;
        const uint32_t bufoff = (uint32_t)b * BUF_BYTES;

        // store A (chunk c) into As[b], fp32 -> fp16
        #pragma unroll
        for (int it = 0; it < 2; it++) {
            int i = tid + it * 512;
            int row = i >> 4, f4 = i & 15;
            __half2 p0 = __floats2half2_rn(av[it].x, av[it].y);
            __half2 p1 = __floats2half2_rn(av[it].z, av[it].w);
            uint2 u;
            u.x = *(const uint32_t*)&p0;
            u.y = *(const uint32_t*)&p1;
            uint32_t byte = (uint32_t)row * 128 +
                            (((uint32_t)f4 * 8) ^ (((uint32_t)row & 7) << 4));
            *(uint2*)(a + bufoff + byte) = u;
        }

        CP_WAIT0();           // B (chunk c) arrived
        __syncthreads();      // buffer b fully populated for all warps

        // issue next chunk's loads (overlap with compute below)
        if (c < 7) {
            const int cn = c + 1;
            const float* src = (cn < 4) ? sre : sim;
            int cb = (cn & 3) * 64;
            #pragma unroll
            for (int it = 0; it < 2; it++) {
                int i = tid + it * 512;
                int row = i >> 4, f4 = i & 15;
                av[it] = *(const float4*)(src + (tileBase + row) * 256 + cb + f4 * 4);
            }
            uint32_t nbuf = (uint32_t)(b ^ 1) * BUF_BYTES;
            #pragma unroll
            for (int it = 0; it < 4; it++) {
                int i = tid + it * 512;
                int n = i >> 3, seg = i & 7;
                uint32_t dst = abase + nbuf + BS_OFF +
                               (uint32_t)n * 128 +
                               (((uint32_t)seg * 16) ^ (((uint32_t)n & 7) << 4));
                cp_async16(dst, Wh_global + n * 512 + cn * 64 + seg * 8);
            }
            CP_COMMIT();
        }

        // compute chunk c: 4 k-steps of 16
        #pragma unroll
        for (int ks = 0; ks < 4; ks++) {
            uint32_t cx = (((uint32_t)ks * 32) | ch16) ^ xorv;
            uint32_t af[2][4];
            #pragma unroll
            for (int mf = 0; mf < 2; mf++)
                ldmatrix_x4(af[mf], aRow[mf] + bufoff + cx);
            uint32_t bf[2][4];
            #pragma unroll
            for (int nb = 0; nb < 2; nb++)
                ldmatrix_x4(bf[nb], bRow[nb] + bufoff + cx);
            #pragma unroll
            for (int mf = 0; mf < 2; mf++)
                #pragma unroll
                for (int nf = 0; nf < 4; nf++) {
                    int nb = nf >> 1, sub = nf & 1;
                    mma16816(acc[mf][nf], af[mf], bf[nb][sub], bf[nb][sub + 2]);
                }
        }
        __syncthreads();      // all warps done with buffer b before overwrite
    }

    // ---- epilogue: out[m] = sum_n C[m][n]^2 ----
    if (tid < 64) red[tid] = 0.0f;
    __syncthreads();

    #pragma unroll
    for (int mf = 0; mf < 2; mf++) {
        float s_lo = 0.0f, s_hi = 0.0f;
        #pragma unroll
        for (int nf = 0; nf < 4; nf++) {
            s_lo = fmaf(acc[mf][nf][0], acc[mf][nf][0], s_lo);
            s_lo = fmaf(acc[mf][nf][1], acc[mf][nf][1], s_lo);
            s_hi = fmaf(acc[mf][nf][2], acc[mf][nf][2], s_hi);
            s_hi = fmaf(acc[mf][nf][3], acc[mf][nf][3], s_hi);
        }
        // reduce over the 4 lanes sharing a row
        s_lo += __shfl_xor_sync(0xFFFFFFFF, s_lo, 1);
        s_lo += __shfl_xor_sync(0xFFFFFFFF, s_lo, 2);
        s_hi += __shfl_xor_sync(0xFFFFFFFF, s_hi, 1);
        s_hi += __shfl_xor_sync(0xFFFFFFFF, s_hi, 2);
        if ((lane & 3) == 0) {
            int row = wm * 32 + mf * 16 + (lane >> 2);
            atomicAdd(red + row, s_lo);
            atomicAdd(red + row + 8, s_hi);
        }
    }
    __syncthreads();
    if (tid < 64) out[tileBase + tid] = red[tid];
}

// ---------------------------------------------------------------------------
extern "C" void kernel_launch(void* const* d_in, const int* in_sizes, int n_in,
                              void* d_out, int out_size) {
    const float* params = (const float*)d_in[0];
    const float* sre    = (const float*)d_in[1];
    const float* sim    = (const float*)d_in[2];
    float* out = (float*)d_out;

    cudaFuncSetAttribute(qmm_kernel, cudaFuncAttributeMaxDynamicSharedMemorySize,
                         DYN_SMEM);

    build_weights_kernel<<<32, 256>>>(params);
    qmm_kernel<<<2048, 512, DYN_SMEM>>>(sre, sim, out);
}

// round 5
// speedup vs baseline: 1.6706x; 1.6706x over previous
#include <cuda_runtime.h>
#include <cuda_fp16.h>
#include <cstdint>

// ============================================================================
// out_i = || P * U(params) * s_i ||^2, 131072 states of dim 256.
// params are batch-invariant -> precompute A = P*U (128x256 complex) once,
// then a real GEMM with fp16 mma.sync (tcgen05 unavailable: harness PTX
// targets compute_103 base, not sm_103a):
//   S = [sr | si]  (131072 x 512 fp32, converted to fp16 on the fly)
//   Wh[n][k] fp16 (256 x 512), n<128: [Ar | -Ai], n>=128: [Ai | Ar]
//   C[m][n] = sum_k S[m][k] Wh[n][k];  out_m = sum_n C[m][n]^2
//
// R5: 2 CTAs/SM with UNCHANGED 64x32 warp tile (R4 shrank it -> regression).
//     CTA = 64 rows x 256 N, 256 threads, warp grid 1x8, 1 sync/chunk.
//     Setup split: build_gates (trig once) + block-per-column simulation.
// ============================================================================

#define NLAYERS 3
#define NQ 8

__device__ __half Wh_global[256 * 512];
__device__ float  Gates[NLAYERS * NQ][8];   // u00r,u00i,u01r,u01i,u10r,u10i,u11r,u11i

// ---------------------------------------------------------------------------
__device__ __forceinline__ uint32_t smem_u32(const void* p) {
    uint32_t a;
    asm("{ .reg .u64 t; cvta.to.shared.u64 t, %1; cvt.u32.u64 %0, t; }"
        : "=r"(a) : "l"(p));
    return a;
}

__device__ __forceinline__ void ldmatrix_x4(uint32_t r[4], uint32_t addr) {
    asm volatile("ldmatrix.sync.aligned.m8n8.x4.shared.b16 {%0,%1,%2,%3}, [%4];"
                 : "=r"(r[0]), "=r"(r[1]), "=r"(r[2]), "=r"(r[3]) : "r"(addr));
}

__device__ __forceinline__ void mma16816(float c[4], const uint32_t a[4],
                                         uint32_t b0, uint32_t b1) {
    asm volatile(
        "mma.sync.aligned.m16n8k16.row.col.f32.f16.f16.f32 "
        "{%0,%1,%2,%3}, {%4,%5,%6,%7}, {%8,%9}, {%0,%1,%2,%3};"
        : "+f"(c[0]), "+f"(c[1]), "+f"(c[2]), "+f"(c[3])
        : "r"(a[0]), "r"(a[1]), "r"(a[2]), "r"(a[3]), "r"(b0), "r"(b1));
}

__device__ __forceinline__ void cp_async16_ca(uint32_t dst, const void* src) {
    asm volatile("cp.async.ca.shared.global [%0], [%1], 16;"
                 :: "r"(dst), "l"(src) : "memory");
}
#define CP_COMMIT() asm volatile("cp.async.commit_group;" ::: "memory")
#define CP_WAIT0()  asm volatile("cp.async.wait_group 0;" ::: "memory")

// ---------------------------------------------------------------------------
// Setup stage 1: 24 gate matrices (all the trig, once).
// ---------------------------------------------------------------------------
__global__ void build_gates_kernel(const float* __restrict__ params) {
    int g = threadIdx.x;
    if (g >= NLAYERS * NQ) return;
    const float* pr = params + g * 3;
    float hx = 0.5f * pr[0], hy = 0.5f * pr[1], hz = 0.5f * pr[2];
    float cx = cosf(hx), sx = sinf(hx);
    float cy = cosf(hy), sy = sinf(hy);
    float cz = cosf(hz), sz = sinf(hz);
    float m00r =  cy * cx, m00i =  sy * sx;
    float m01r = -sy * cx, m01i = -cy * sx;
    float m10r =  sy * cx, m10i = -cy * sx;
    float m11r =  cy * cx, m11i = -sy * sx;
    Gates[g][0] = cz * m00r + sz * m00i;  Gates[g][1] = cz * m00i - sz * m00r;
    Gates[g][2] = cz * m01r + sz * m01i;  Gates[g][3] = cz * m01i - sz * m01r;
    Gates[g][4] = cz * m10r - sz * m10i;  Gates[g][5] = cz * m10i + sz * m10r;
    Gates[g][6] = cz * m11r - sz * m11i;  Gates[g][7] = cz * m11i + sz * m11r;
}

// ---------------------------------------------------------------------------
// Setup stage 2: simulate circuit on basis states; block k -> column k of U.
// Trig-free: gate matrices read from Gates[].
// ---------------------------------------------------------------------------
__global__ void build_weights_kernel() {
    __shared__ float2 st[256];
    int k = blockIdx.x;
    int t = threadIdx.x;

    st[t] = make_float2(t == k ? 1.0f : 0.0f, 0.0f);

    for (int l = 0; l < NLAYERS; l++) {
        for (int q = 0; q < NQ; q++) {
            const float* u = Gates[l * NQ + q];
            float u00r = u[0], u00i = u[1], u01r = u[2], u01i = u[3];
            float u10r = u[4], u10i = u[5], u11r = u[6], u11i = u[7];
            int p = 7 - q;  // qubit 0 = MSB of the flat index
            __syncthreads();
            if (t < 128) {
                int lo = t & ((1 << p) - 1);
                int i0 = ((t >> p) << (p + 1)) | lo;
                int i1 = i0 | (1 << p);
                float2 a0 = st[i0], a1 = st[i1];
                float2 n0, n1;
                n0.x = u00r*a0.x - u00i*a0.y + u01r*a1.x - u01i*a1.y;
                n0.y = u00r*a0.y + u00i*a0.x + u01r*a1.y + u01i*a1.x;
                n1.x = u10r*a0.x - u10i*a0.y + u11r*a1.x - u11i*a1.y;
                n1.y = u10r*a0.y + u10i*a0.x + u11r*a1.y + u11i*a1.x;
                st[i0] = n0;
                st[i1] = n1;
            }
        }
        for (int q = 0; q < NQ; q++) {
            int pc = 7 - q;
            int pt = 7 - ((q + 1) & 7);
            __syncthreads();
            if (((t >> pc) & 1) == 1 && ((t >> pt) & 1) == 0) {
                int j = t | (1 << pt);
                float2 tmp = st[t];
                st[t] = st[j];
                st[j] = tmp;
            }
        }
    }
    __syncthreads();
    if (t < 128) {
        float re = st[t].x, im = st[t].y;
        Wh_global[t * 512 + k]               = __float2half_rn(re);
        Wh_global[t * 512 + 256 + k]         = __float2half_rn(-im);
        Wh_global[(128 + t) * 512 + k]       = __float2half_rn(im);
        Wh_global[(128 + t) * 512 + 256 + k] = __float2half_rn(re);
    }
}

// ---------------------------------------------------------------------------
// GEMM kernel: CTA = 64 batch rows x 256 N. 256 threads = 8 warps,
// warp grid 1(M) x 8(N), warp tile 64x32 (same as the fast R3 config).
// K = 512 in 8 chunks of 64.
// SMEM per buffer: A 64x64 fp16 (8KB, 128B swizzled rows) at +0,
//                  B 256x64 fp16 (32KB) at +8KB. Two buffers (80KB).
// 2 CTAs/SM (regs capped at 128 via launch_bounds(256,2)).
// ---------------------------------------------------------------------------
static constexpr uint32_t BS_OFF    = 8 * 1024;
static constexpr uint32_t BUF_BYTES = 40 * 1024;
static constexpr uint32_t RED_OFF   = 80 * 1024;
static constexpr uint32_t DYN_SMEM  = 80 * 1024 + 256 + 1024;

__global__ void __launch_bounds__(256, 2)
qmm_kernel(const float* __restrict__ sre, const float* __restrict__ sim,
           float* __restrict__ out) {
    extern __shared__ char smem_raw[];
    uint32_t base  = smem_u32(smem_raw);
    uint32_t abase = (base + 1023u) & ~1023u;
    char* a = smem_raw + (abase - base);
    float* red = (float*)(a + RED_OFF);

    const int tid  = threadIdx.x;
    const int wid  = tid >> 5;
    const int lane = tid & 31;
    const int wn   = wid;       // n-slice: cols wn*32..+31

    // ldmatrix per-lane geometry
    const int r  = lane & 7;
    const int q  = lane >> 3;
    const uint32_t xorv = (uint32_t)r << 4;
    const uint32_t ch16 = (uint32_t)(q >> 1) << 4;
    const int rl = ((q & 1) << 3) + r;  // row within 16-row fragment

    uint32_t aRow[4], bRow[2];
    #pragma unroll
    for (int mf = 0; mf < 4; mf++)
        aRow[mf] = abase + (uint32_t)(mf * 16 + rl) * 128;
    #pragma unroll
    for (int nb = 0; nb < 2; nb++)
        bRow[nb] = abase + BS_OFF + (uint32_t)(wn * 32 + nb * 16 + rl) * 128;

    const long tileBase = (long)blockIdx.x * 64;

    float acc[4][4][4];
    #pragma unroll
    for (int mf = 0; mf < 4; mf++)
        #pragma unroll
        for (int nf = 0; nf < 4; nf++)
            #pragma unroll
            for (int i = 0; i < 4; i++) acc[mf][nf][i] = 0.0f;

    // A prefetch: 64 rows x 16 float4 = 1024 float4, 256 thr -> 4/thread.
    // i = tid + it*256 -> row = i>>4, f4 = i&15.
    float4 av[4];

    // ---- prologue: chunk 0 ----
    {
        #pragma unroll
        for (int it = 0; it < 4; it++) {
            int i = tid + it * 256;
            int row = i >> 4, f4 = i & 15;
            av[it] = *(const float4*)(sre + (tileBase + row) * 256 + f4 * 4);
        }
        // B: 256 rows x 8 segs of 16B = 2048 cps, 256 thr -> 8/thread
        #pragma unroll
        for (int it = 0; it < 8; it++) {
            int i = tid + it * 256;
            int n = i >> 3, seg = i & 7;
            uint32_t dst = abase + BS_OFF +
                           (uint32_t)n * 128 +
                           (((uint32_t)seg * 16) ^ (((uint32_t)n & 7) << 4));
            cp_async16_ca(dst, Wh_global + n * 512 + seg * 8);
        }
        CP_COMMIT();
    }

    for (int c = 0; c < 8; c++) {
        const int b = c & 1;
        const uint32_t bufoff = (uint32_t)b * BUF_BYTES;

        // store A (chunk c) into As[b], fp32 -> fp16
        #pragma unroll
        for (int it = 0; it < 4; it++) {
            int i = tid + it * 256;
            int row = i >> 4, f4 = i & 15;
            __half2 p0 = __floats2half2_rn(av[it].x, av[it].y);
            __half2 p1 = __floats2half2_rn(av[it].z, av[it].w);
            uint2 u;
            u.x = *(const uint32_t*)&p0;
            u.y = *(const uint32_t*)&p1;
            uint32_t byte = (uint32_t)row * 128 +
                            (((uint32_t)f4 * 8) ^ (((uint32_t)row & 7) << 4));
            *(uint2*)(a + bufoff + byte) = u;
        }

        CP_WAIT0();           // B (chunk c) arrived
        __syncthreads();      // buffer b fully populated; all warps past chunk c-1

        // issue next chunk's loads (overlap with compute below)
        if (c < 7) {
            const int cn = c + 1;
            const float* src = (cn < 4) ? sre : sim;
            int cb = (cn & 3) * 64;
            #pragma unroll
            for (int it = 0; it < 4; it++) {
                int i = tid + it * 256;
                int row = i >> 4, f4 = i & 15;
                av[it] = *(const float4*)(src + (tileBase + row) * 256 + cb + f4 * 4);
            }
            uint32_t nbuf = (uint32_t)(b ^ 1) * BUF_BYTES;
            #pragma unroll
            for (int it = 0; it < 8; it++) {
                int i = tid + it * 256;
                int n = i >> 3, seg = i & 7;
                uint32_t dst = abase + nbuf + BS_OFF +
                               (uint32_t)n * 128 +
                               (((uint32_t)seg * 16) ^ (((uint32_t)n & 7) << 4));
                cp_async16_ca(dst, Wh_global + n * 512 + cn * 64 + seg * 8);
            }
            CP_COMMIT();
        }

        // compute chunk c: 4 k-steps of 16
        #pragma unroll
        for (int ks = 0; ks < 4; ks++) {
            uint32_t cx = (((uint32_t)ks * 32) | ch16) ^ xorv;
            uint32_t af[4][4];
            #pragma unroll
            for (int mf = 0; mf < 4; mf++)
                ldmatrix_x4(af[mf], aRow[mf] + bufoff + cx);
            uint32_t bf[2][4];
            #pragma unroll
            for (int nb = 0; nb < 2; nb++)
                ldmatrix_x4(bf[nb], bRow[nb] + bufoff + cx);
            #pragma unroll
            for (int mf = 0; mf < 4; mf++)
                #pragma unroll
                for (int nf = 0; nf < 4; nf++) {
                    int nb = nf >> 1, sub = nf & 1;
                    mma16816(acc[mf][nf], af[mf], bf[nb][sub], bf[nb][sub + 2]);
                }
        }
    }

    // ---- epilogue: out[m] = sum_n C[m][n]^2 ----
    __syncthreads();
    if (tid < 64) red[tid] = 0.0f;
    __syncthreads();

    #pragma unroll
    for (int mf = 0; mf < 4; mf++) {
        float s_lo = 0.0f, s_hi = 0.0f;
        #pragma unroll
        for (int nf = 0; nf < 4; nf++) {
            s_lo = fmaf(acc[mf][nf][0], acc[mf][nf][0], s_lo);
            s_lo = fmaf(acc[mf][nf][1], acc[mf][nf][1], s_lo);
            s_hi = fmaf(acc[mf][nf][2], acc[mf][nf][2], s_hi);
            s_hi = fmaf(acc[mf][nf][3], acc[mf][nf][3], s_hi);
        }
        // reduce over the 4 lanes sharing a row
        s_lo += __shfl_xor_sync(0xFFFFFFFF, s_lo, 1);
        s_lo += __shfl_xor_sync(0xFFFFFFFF, s_lo, 2);
        s_hi += __shfl_xor_sync(0xFFFFFFFF, s_hi, 1);
        s_hi += __shfl_xor_sync(0xFFFFFFFF, s_hi, 2);
        if ((lane & 3) == 0) {
            int row = mf * 16 + (lane >> 2);
            atomicAdd(red + row, s_lo);
            atomicAdd(red + row + 8, s_hi);
        }
    }
    __syncthreads();
    if (tid < 64) out[tileBase + tid] = red[tid];
}

// ---------------------------------------------------------------------------
extern "C" void kernel_launch(void* const* d_in, const int* in_sizes, int n_in,
                              void* d_out, int out_size) {
    const float* params = (const float*)d_in[0];
    const float* sre    = (const float*)d_in[1];
    const float* sim    = (const float*)d_in[2];
    float* out = (float*)d_out;

    cudaFuncSetAttribute(qmm_kernel, cudaFuncAttributeMaxDynamicSharedMemorySize,
                         DYN_SMEM);

    build_gates_kernel<<<1, 32>>>(params);
    build_weights_kernel<<<256, 256>>>();
    qmm_kernel<<<2048, 256, DYN_SMEM>>>(sre, sim, out);
}

// round 6
// speedup vs baseline: 1.9505x; 1.1676x over previous
#include <cuda_runtime.h>
#include <cuda_fp16.h>
#include <cstdint>

// ============================================================================
// out_i = || P * U(params) * s_i ||^2, 131072 states of dim 256.
// params batch-invariant -> precompute A = P*U (128x256 complex), then a real
// fp16 mma.sync GEMM (tcgen05 unavailable on compute_103 base target):
//   S = [sr | si] (131072 x 512 fp32 -> fp16 on the fly)
//   Wh[n][k] fp16 (256 x 512), n<128: [Ar | -Ai], n>=128: [Ai | Ar]
//   C[m][n] = sum_k S[m][k] Wh[n][k];  out_m = sum_n C[m][n]^2
//
// R6: L1TEX-wavefront model fix. Warp tile 64x64 (LDSM wf per MMA 0.75->0.5),
//     CTA 128x256, 8 warps, full register budget (1 CTA/SM). 4-stage cp.async
//     ring for B, 2-stage register prefetch for A. Setup fused to one kernel.
// ============================================================================

#define NLAYERS 3
#define NQ 8

__device__ __half Wh_global[256 * 512];

// ---------------------------------------------------------------------------
__device__ __forceinline__ uint32_t smem_u32(const void* p) {
    uint32_t a;
    asm("{ .reg .u64 t; cvta.to.shared.u64 t, %1; cvt.u32.u64 %0, t; }"
        : "=r"(a) : "l"(p));
    return a;
}

__device__ __forceinline__ void ldmatrix_x4(uint32_t r[4], uint32_t addr) {
    asm volatile("ldmatrix.sync.aligned.m8n8.x4.shared.b16 {%0,%1,%2,%3}, [%4];"
                 : "=r"(r[0]), "=r"(r[1]), "=r"(r[2]), "=r"(r[3]) : "r"(addr));
}

__device__ __forceinline__ void mma16816(float c[4], const uint32_t a[4],
                                         uint32_t b0, uint32_t b1) {
    asm volatile(
        "mma.sync.aligned.m16n8k16.row.col.f32.f16.f16.f32 "
        "{%0,%1,%2,%3}, {%4,%5,%6,%7}, {%8,%9}, {%0,%1,%2,%3};"
        : "+f"(c[0]), "+f"(c[1]), "+f"(c[2]), "+f"(c[3])
        : "r"(a[0]), "r"(a[1]), "r"(a[2]), "r"(a[3]), "r"(b0), "r"(b1));
}

__device__ __forceinline__ void cp_async16(uint32_t dst, const void* src) {
    asm volatile("cp.async.cg.shared.global [%0], [%1], 16;"
                 :: "r"(dst), "l"(src) : "memory");
}
#define CP_COMMIT() asm volatile("cp.async.commit_group;" ::: "memory")
#define CP_WAIT(n)  asm volatile("cp.async.wait_group %0;" :: "n"(n) : "memory")

// ---------------------------------------------------------------------------
// Setup (single kernel): block k simulates basis state |k>. Gate matrices
// computed once per block into smem (24 gates, trivial trig).
// ---------------------------------------------------------------------------
__global__ void build_weights_kernel(const float* __restrict__ params) {
    __shared__ float2 st[256];
    __shared__ float g[NLAYERS * NQ][8];
    int k = blockIdx.x;
    int t = threadIdx.x;

    if (t < NLAYERS * NQ) {
        const float* pr = params + t * 3;
        float hx = 0.5f * pr[0], hy = 0.5f * pr[1], hz = 0.5f * pr[2];
        float cx = cosf(hx), sx = sinf(hx);
        float cy = cosf(hy), sy = sinf(hy);
        float cz = cosf(hz), sz = sinf(hz);
        float m00r =  cy * cx, m00i =  sy * sx;
        float m01r = -sy * cx, m01i = -cy * sx;
        float m10r =  sy * cx, m10i = -cy * sx;
        float m11r =  cy * cx, m11i = -sy * sx;
        g[t][0] = cz * m00r + sz * m00i;  g[t][1] = cz * m00i - sz * m00r;
        g[t][2] = cz * m01r + sz * m01i;  g[t][3] = cz * m01i - sz * m01r;
        g[t][4] = cz * m10r - sz * m10i;  g[t][5] = cz * m10i + sz * m10r;
        g[t][6] = cz * m11r - sz * m11i;  g[t][7] = cz * m11i + sz * m11r;
    }
    st[t] = make_float2(t == k ? 1.0f : 0.0f, 0.0f);
    __syncthreads();

    for (int l = 0; l < NLAYERS; l++) {
        for (int q = 0; q < NQ; q++) {
            const float* u = g[l * NQ + q];
            float u00r = u[0], u00i = u[1], u01r = u[2], u01i = u[3];
            float u10r = u[4], u10i = u[5], u11r = u[6], u11i = u[7];
            int p = 7 - q;  // qubit 0 = MSB of flat index
            if (t < 128) {
                int lo = t & ((1 << p) - 1);
                int i0 = ((t >> p) << (p + 1)) | lo;
                int i1 = i0 | (1 << p);
                float2 a0 = st[i0], a1 = st[i1];
                float2 n0, n1;
                n0.x = u00r*a0.x - u00i*a0.y + u01r*a1.x - u01i*a1.y;
                n0.y = u00r*a0.y + u00i*a0.x + u01r*a1.y + u01i*a1.x;
                n1.x = u10r*a0.x - u10i*a0.y + u11r*a1.x - u11i*a1.y;
                n1.y = u10r*a0.y + u10i*a0.x + u11r*a1.y + u11i*a1.x;
                st[i0] = n0;
                st[i1] = n1;
            }
            __syncthreads();
        }
        for (int q = 0; q < NQ; q++) {
            int pc = 7 - q;
            int pt = 7 - ((q + 1) & 7);
            if (((t >> pc) & 1) == 1 && ((t >> pt) & 1) == 0) {
                int j = t | (1 << pt);
                float2 tmp = st[t];
                st[t] = st[j];
                st[j] = tmp;
            }
            __syncthreads();
        }
    }
    if (t < 128) {
        float re = st[t].x, im = st[t].y;
        Wh_global[t * 512 + k]               = __float2half_rn(re);
        Wh_global[t * 512 + 256 + k]         = __float2half_rn(-im);
        Wh_global[(128 + t) * 512 + k]       = __float2half_rn(im);
        Wh_global[(128 + t) * 512 + 256 + k] = __float2half_rn(re);
    }
}

// ---------------------------------------------------------------------------
// GEMM: CTA = 128 rows x 256 N, 256 threads = 8 warps, warp grid 2(M) x 4(N),
// warp tile 64x64. K = 512 in 8 chunks of 64.
// SMEM: A fp16 128x64 = 16KB x 2 stages at 0;  B fp16 256x64 = 32KB x 4
// stages at 32KB; red[128] at 160KB. 1 CTA/SM, full register budget.
// ---------------------------------------------------------------------------
static constexpr uint32_t SA_STAGE = 16 * 1024;
static constexpr uint32_t SB_OFF   = 32 * 1024;
static constexpr uint32_t SB_STAGE = 32 * 1024;
static constexpr uint32_t RED_OFF  = 160 * 1024;
static constexpr uint32_t DYN_SMEM = 160 * 1024 + 512 + 1024;

__global__ void __launch_bounds__(256, 1)
qmm_kernel(const float* __restrict__ sre, const float* __restrict__ sim,
           float* __restrict__ out) {
    extern __shared__ char smem_raw[];
    uint32_t base  = smem_u32(smem_raw);
    uint32_t abase = (base + 1023u) & ~1023u;
    char* a = smem_raw + (abase - base);
    float* red = (float*)(a + RED_OFF);

    const int tid  = threadIdx.x;
    const int wid  = tid >> 5;
    const int lane = tid & 31;
    const int wm   = wid >> 2;  // 0..1 : rows wm*64..+63
    const int wn   = wid & 3;   // 0..3 : cols wn*64..+63

    // ldmatrix per-lane geometry (validated in R3/R5)
    const int r  = lane & 7;
    const int q  = lane >> 3;
    const uint32_t xorv = (uint32_t)r << 4;
    const uint32_t ch16 = (uint32_t)(q >> 1) << 4;
    const int rl = ((q & 1) << 3) + r;

    uint32_t aRow[4], bRow[4];
    #pragma unroll
    for (int mf = 0; mf < 4; mf++)
        aRow[mf] = abase + (uint32_t)(wm * 64 + mf * 16 + rl) * 128;
    #pragma unroll
    for (int nb = 0; nb < 4; nb++)
        bRow[nb] = abase + SB_OFF + (uint32_t)(wn * 64 + nb * 16 + rl) * 128;

    const long tileBase = (long)blockIdx.x * 128;

    float acc[4][8][4];
    #pragma unroll
    for (int mf = 0; mf < 4; mf++)
        #pragma unroll
        for (int nf = 0; nf < 8; nf++)
            #pragma unroll
            for (int i = 0; i < 4; i++) acc[mf][nf][i] = 0.0f;

    // A prefetch: 128 rows x 16 float4 = 2048, 256 thr -> 8/thread.
    float4 av[8];

    // ---- prologue ----
    {
        #pragma unroll
        for (int it = 0; it < 8; it++) {
            int i = tid + it * 256;
            int row = i >> 4, f4 = i & 15;
            av[it] = *(const float4*)(sre + (tileBase + row) * 256 + f4 * 4);
        }
        #pragma unroll
        for (int cc = 0; cc < 2; cc++) {
            uint32_t sb = abase + SB_OFF + (uint32_t)cc * SB_STAGE;
            #pragma unroll
            for (int it = 0; it < 8; it++) {
                int i = tid + it * 256;
                int n = i >> 3, seg = i & 7;
                uint32_t dst = sb + (uint32_t)n * 128 +
                               (((uint32_t)seg * 16) ^ (((uint32_t)n & 7) << 4));
                cp_async16(dst, Wh_global + n * 512 + cc * 64 + seg * 8);
            }
            CP_COMMIT();
        }
    }

    for (int c = 0; c < 8; c++) {
        const uint32_t saoff = (uint32_t)(c & 1) * SA_STAGE;
        const uint32_t sboff = (uint32_t)(c & 3) * SB_STAGE;

        // store A(c) regs -> smem, fp32 -> fp16
        #pragma unroll
        for (int it = 0; it < 8; it++) {
            int i = tid + it * 256;
            int row = i >> 4, f4 = i & 15;
            __half2 p0 = __floats2half2_rn(av[it].x, av[it].y);
            __half2 p1 = __floats2half2_rn(av[it].z, av[it].w);
            uint2 u;
            u.x = *(const uint32_t*)&p0;
            u.y = *(const uint32_t*)&p1;
            uint32_t byte = (uint32_t)row * 128 +
                            (((uint32_t)f4 * 8) ^ (((uint32_t)row & 7) << 4));
            *(uint2*)(a + saoff + byte) = u;
        }

        // issue B(c+2) into stage (c+2)&3 (dummy commit keeps group count uniform)
        if (c + 2 < 8) {
            uint32_t sb = abase + SB_OFF + (uint32_t)((c + 2) & 3) * SB_STAGE;
            #pragma unroll
            for (int it = 0; it < 8; it++) {
                int i = tid + it * 256;
                int n = i >> 3, seg = i & 7;
                uint32_t dst = sb + (uint32_t)n * 128 +
                               (((uint32_t)seg * 16) ^ (((uint32_t)n & 7) << 4));
                cp_async16(dst, Wh_global + n * 512 + (c + 2) * 64 + seg * 8);
            }
        }
        CP_COMMIT();

        // prefetch A(c+1) into regs
        if (c < 7) {
            const int cn = c + 1;
            const float* src = (cn < 4) ? sre : sim;
            int cb = (cn & 3) * 64;
            #pragma unroll
            for (int it = 0; it < 8; it++) {
                int i = tid + it * 256;
                int row = i >> 4, f4 = i & 15;
                av[it] = *(const float4*)(src + (tileBase + row) * 256 + cb + f4 * 4);
            }
        }

        CP_WAIT(2);           // groups <= c complete (c+1, c+2 may be in flight)
        __syncthreads();      // A(c) stores + B(c) visible to all warps

        // compute chunk c: 4 k-steps of 16
        #pragma unroll
        for (int ks = 0; ks < 4; ks++) {
            uint32_t cx = (((uint32_t)ks * 32) | ch16) ^ xorv;
            uint32_t af[4][4];
            #pragma unroll
            for (int mf = 0; mf < 4; mf++)
                ldmatrix_x4(af[mf], aRow[mf] + saoff + cx);
            uint32_t bf[4][4];
            #pragma unroll
            for (int nb = 0; nb < 4; nb++)
                ldmatrix_x4(bf[nb], bRow[nb] + sboff + cx);
            #pragma unroll
            for (int mf = 0; mf < 4; mf++)
                #pragma unroll
                for (int nf = 0; nf < 8; nf++) {
                    int nb = nf >> 1, sub = nf & 1;
                    mma16816(acc[mf][nf], af[mf], bf[nb][sub], bf[nb][sub + 2]);
                }
        }
    }

    // ---- epilogue: out[m] = sum_n C[m][n]^2 ----
    __syncthreads();
    if (tid < 128) red[tid] = 0.0f;
    __syncthreads();

    #pragma unroll
    for (int mf = 0; mf < 4; mf++) {
        float s_lo = 0.0f, s_hi = 0.0f;
        #pragma unroll
        for (int nf = 0; nf < 8; nf++) {
            s_lo = fmaf(acc[mf][nf][0], acc[mf][nf][0], s_lo);
            s_lo = fmaf(acc[mf][nf][1], acc[mf][nf][1], s_lo);
            s_hi = fmaf(acc[mf][nf][2], acc[mf][nf][2], s_hi);
            s_hi = fmaf(acc[mf][nf][3], acc[mf][nf][3], s_hi);
        }
        s_lo += __shfl_xor_sync(0xFFFFFFFF, s_lo, 1);
        s_lo += __shfl_xor_sync(0xFFFFFFFF, s_lo, 2);
        s_hi += __shfl_xor_sync(0xFFFFFFFF, s_hi, 1);
        s_hi += __shfl_xor_sync(0xFFFFFFFF, s_hi, 2);
        if ((lane & 3) == 0) {
            int row = wm * 64 + mf * 16 + (lane >> 2);
            atomicAdd(red + row, s_lo);
            atomicAdd(red + row + 8, s_hi);
        }
    }
    __syncthreads();
    if (tid < 128) out[tileBase + tid] = red[tid];
}

// ---------------------------------------------------------------------------
extern "C" void kernel_launch(void* const* d_in, const int* in_sizes, int n_in,
                              void* d_out, int out_size) {
    const float* params = (const float*)d_in[0];
    const float* sre    = (const float*)d_in[1];
    const float* sim    = (const float*)d_in[2];
    float* out = (float*)d_out;

    cudaFuncSetAttribute(qmm_kernel, cudaFuncAttributeMaxDynamicSharedMemorySize,
                         DYN_SMEM);

    build_weights_kernel<<<256, 256>>>(params);
    qmm_kernel<<<1024, 256, DYN_SMEM>>>(sre, sim, out);
}